// round 3
// baseline (speedup 1.0000x reference)
#include <cuda_runtime.h>

#define C_CH 32
#define HW   256
#define KS2  9
#define OCH  288
#define QS   32
#define NB   4

__device__ float g_p[NB * C_CH * QS * QS];   // [n][c][32][32]
__device__ float g_y[NB * OCH * QS * QS];    // [n][o][32][32]

// ---------------------------------------------------------------------------
// Kernel A: psf -> bilinear 1/4 (exact 2x2 means) -> maxpool2 -> g_p
// ---------------------------------------------------------------------------
__global__ void kA(const float* __restrict__ psf) {
    int t = blockIdx.x * blockDim.x + threadIdx.x;   // 131072
    int j = t & 31;
    int i = (t >> 5) & 31;
    int c = (t >> 10) & 31;
    int n = t >> 15;
    const float* base = psf + ((size_t)(n * C_CH + c) * HW) * HW;

    const int rr[4] = {8 * i + 1, 8 * i + 2, 8 * i + 5, 8 * i + 6};
    const int cc[4] = {8 * j + 1, 8 * j + 2, 8 * j + 5, 8 * j + 6};
    float v[4][4];
#pragma unroll
    for (int a = 0; a < 4; a++)
#pragma unroll
        for (int b = 0; b < 4; b++)
            v[a][b] = __ldg(base + rr[a] * HW + cc[b]);

    float s00 = v[0][0] + v[0][1] + v[1][0] + v[1][1];
    float s01 = v[0][2] + v[0][3] + v[1][2] + v[1][3];
    float s10 = v[2][0] + v[2][1] + v[3][0] + v[3][1];
    float s11 = v[2][2] + v[2][3] + v[3][2] + v[3][3];
    g_p[t] = 0.25f * fmaxf(fmaxf(s00, s01), fmaxf(s10, s11));
}

// ---------------------------------------------------------------------------
// Kernel B: thread = (n, c_out, pix); caches 32-ch p column in registers,
// computes all 9 taps -> g_y. float4 weight loads, 4 accumulators.
// ---------------------------------------------------------------------------
__global__ void __launch_bounds__(256) kB(const float* __restrict__ w1,
                                          const float* __restrict__ b1,
                                          const float* __restrict__ ws,
                                          const float* __restrict__ bs) {
    int t = blockIdx.x * blockDim.x + threadIdx.x;   // 4*32*1024 = 131072
    int pix = t & 1023;
    int c = (t >> 10) & 31;
    int n = t >> 15;

    float pv[C_CH];
    const float* pb = g_p + (size_t)n * (C_CH * QS * QS) + pix;
#pragma unroll
    for (int ch = 0; ch < C_CH; ch++) pv[ch] = pb[ch * (QS * QS)];

    float* yb = g_y + (size_t)(n * OCH + c * KS2) * (QS * QS) + pix;
#pragma unroll
    for (int k = 0; k < KS2; k++) {
        const int o = c * KS2 + k;
        const float4* wr1 = (const float4*)(w1 + o * C_CH);
        const float4* wrs = (const float4*)(ws + o * C_CH);
        float a1lo = 0.f, a1hi = 0.f, a2lo = 0.f, a2hi = 0.f;
#pragma unroll
        for (int q = 0; q < C_CH / 4; q++) {
            float4 u = __ldg(wr1 + q);
            float4 s = __ldg(wrs + q);
            int ch = 4 * q;
            a1lo = fmaf(pv[ch + 0], u.x, a1lo);
            a1hi = fmaf(pv[ch + 1], u.y, a1hi);
            a1lo = fmaf(pv[ch + 2], u.z, a1lo);
            a1hi = fmaf(pv[ch + 3], u.w, a1hi);
            a2lo = fmaf(pv[ch + 0], s.x, a2lo);
            a2hi = fmaf(pv[ch + 1], s.y, a2hi);
            a2lo = fmaf(pv[ch + 2], s.z, a2lo);
            a2hi = fmaf(pv[ch + 3], s.w, a2hi);
        }
        float a1 = a1lo + a1hi + b1[o];
        float a2 = a2lo + a2hi + bs[o];
        float act = (a1 >= 0.f) ? a1 : 0.2f * a1;
        yb[k * (QS * QS)] = act + a2;
    }
}

// ---------------------------------------------------------------------------
// Kernel C: fused x8 bilinear upsample + FAC 3x3, 32-row tiles.
// Lazy hl (rolling hlA/hlB), 4 FMA accumulators, reg-capped for 5 blk/SM.
// ---------------------------------------------------------------------------
__global__ void __launch_bounds__(256, 5) kC(const float* __restrict__ fm,
                                             float* __restrict__ out) {
    __shared__ float fmt[34][258];       // fm rows h0-1 .. h0+32, cols -1..256
    __shared__ float yt[6][KS2][32];     // 6 coarse rows x 9 taps x 32 cols

    const int tt = blockIdx.x;           // 0..7 (32-row tiles)
    const int c  = blockIdx.y;
    const int n  = blockIdx.z;
    const int w  = threadIdx.x;
    const int h0 = tt * 32;
    const int crBase = 4 * tt - 1;

    // ---- stage featuremap tile (zero-padded ring) ----
    const float* fbase = fm + ((size_t)(n * C_CH + c) * HW) * HW;
#pragma unroll
    for (int r = 0; r < 34; r++) {
        int gh = h0 - 1 + r;
        bool rowok = (gh >= 0) && (gh < HW);
        for (int col = w; col < 258; col += 256) {
            int gw = col - 1;
            float v = 0.f;
            if (rowok && gw >= 0 && gw < HW) v = fbase[gh * HW + gw];
            fmt[r][col] = v;
        }
    }

    // ---- stage coarse filter rows (row-clamped) ----
    const float* ybase = g_y + (size_t)(n * OCH + c * KS2) * (QS * QS);
    for (int idx = w; idx < 6 * KS2 * 32; idx += 256) {
        int col = idx & 31;
        int q = idx >> 5;                // 0..53
        int r = q / KS2;
        int k = q - r * KS2;
        int cr = min(max(crBase + r, 0), QS - 1);
        yt[r][k][col] = ybase[k * (QS * QS) + cr * QS + col];
    }
    __syncthreads();

    // ---- horizontal lerp setup ----
    int ix0 = (w - 4) >> 3;
    float wx = (float)w * 0.125f - 0.4375f - (float)ix0;
    const int jx0 = max(ix0, 0);
    const int jx1 = min(ix0 + 1, QS - 1);

    float hlA[KS2], hlB[KS2];
    auto refresh = [&](float* dst, int r) {
#pragma unroll
        for (int k = 0; k < KS2; k++) {
            float a = yt[r][k][jx0];
            float b = yt[r][k][jx1];
            dst[k] = fmaf(wx, b - a, a);
        }
    };
    refresh(hlA, 0);
    refresh(hlB, 1);

    // ---- rolling 3x3 window + vertical lerp + FAC ----
    float win[3][3];
#pragma unroll
    for (int d = 0; d < 3; d++) {
        win[0][d] = fmt[0][w + d];
        win[1][d] = fmt[1][w + d];
    }

    float* obase = out + (((size_t)(n * C_CH + c) * HW + h0) * HW) + w;

    auto doRow = [&](int hh, float wy) {
#pragma unroll
        for (int d = 0; d < 3; d++) win[2][d] = fmt[hh + 2][w + d];
        float d0a = 0.f, d0b = 0.f, d1a = 0.f, d1b = 0.f;
        // taps 0..4 on 'a' chains, 5..8 on 'b' chains
        d0a = fmaf(hlA[0], win[0][0], d0a);  d1a = fmaf(hlB[0], win[0][0], d1a);
        d0a = fmaf(hlA[1], win[0][1], d0a);  d1a = fmaf(hlB[1], win[0][1], d1a);
        d0a = fmaf(hlA[2], win[0][2], d0a);  d1a = fmaf(hlB[2], win[0][2], d1a);
        d0a = fmaf(hlA[3], win[1][0], d0a);  d1a = fmaf(hlB[3], win[1][0], d1a);
        d0a = fmaf(hlA[4], win[1][1], d0a);  d1a = fmaf(hlB[4], win[1][1], d1a);
        d0b = fmaf(hlA[5], win[1][2], d0b);  d1b = fmaf(hlB[5], win[1][2], d1b);
        d0b = fmaf(hlA[6], win[2][0], d0b);  d1b = fmaf(hlB[6], win[2][0], d1b);
        d0b = fmaf(hlA[7], win[2][1], d0b);  d1b = fmaf(hlB[7], win[2][1], d1b);
        d0b = fmaf(hlA[8], win[2][2], d0b);  d1b = fmaf(hlB[8], win[2][2], d1b);
        float dot0 = d0a + d0b;
        float dot1 = d1a + d1b;
        obase[hh * HW] = fmaf(wy, dot1 - dot0, dot0);
#pragma unroll
        for (int d = 0; d < 3; d++) {
            win[0][d] = win[1][d];
            win[1][d] = win[2][d];
        }
    };
    auto shiftUp = [&](int newRow) {
#pragma unroll
        for (int k = 0; k < KS2; k++) hlA[k] = hlB[k];
        refresh(hlB, newRow);
    };

    // segment 0: hh 0..3, t0=0 (staged rows 0,1)
#pragma unroll
    for (int hh = 0; hh < 4; hh++)  doRow(hh, (float)hh * 0.125f + 0.5625f);
    shiftUp(2);   // t0=1
#pragma unroll
    for (int hh = 4; hh < 12; hh++) doRow(hh, (float)hh * 0.125f - 0.4375f);
    shiftUp(3);   // t0=2
#pragma unroll
    for (int hh = 12; hh < 20; hh++) doRow(hh, (float)hh * 0.125f - 1.4375f);
    shiftUp(4);   // t0=3
#pragma unroll
    for (int hh = 20; hh < 28; hh++) doRow(hh, (float)hh * 0.125f - 2.4375f);
    shiftUp(5);   // t0=4
#pragma unroll
    for (int hh = 28; hh < 32; hh++) doRow(hh, (float)hh * 0.125f - 3.4375f);
}

// ---------------------------------------------------------------------------
extern "C" void kernel_launch(void* const* d_in, const int* in_sizes, int n_in,
                              void* d_out, int out_size) {
    const float* psf = (const float*)d_in[0];
    const float* fm  = (const float*)d_in[1];
    const float* w1  = (const float*)d_in[2];
    const float* b1  = (const float*)d_in[3];
    const float* ws  = (const float*)d_in[4];
    const float* bs  = (const float*)d_in[5];
    float* out = (float*)d_out;

    kA<<<512, 256>>>(psf);
    kB<<<512, 256>>>(w1, b1, ws, bs);
    dim3 gc(8, C_CH, NB);
    kC<<<gc, 256>>>(fm, out);
}

// round 4
// speedup vs baseline: 1.1669x; 1.1669x over previous
#include <cuda_runtime.h>

#define C_CH 32
#define HW   256
#define KS2  9
#define OCH  288
#define QS   32
#define NB   4

__device__ float g_p[NB * C_CH * QS * QS];   // [n][c][32][32]
__device__ float g_y[NB * OCH * QS * QS];    // [n][o][32][32]

// ---------------------------------------------------------------------------
// Kernel A: warp-per-output-row. psf -> bilinear 1/4 -> maxpool2 -> g_p.
// Each lane loads 4 rows x 2 float4 (coalesced LDG.128); cols 4L+1,4L+2 are
// the exact bilinear 2-col pair. Quadrant max via one shfl_xor.
// ---------------------------------------------------------------------------
__global__ void kA(const float* __restrict__ psf) {
    const int g    = (blockIdx.x * blockDim.x + threadIdx.x) >> 5; // 0..4095
    const int lane = threadIdx.x & 31;
    const int i = g & 31;
    const int c = (g >> 5) & 31;
    const int n = g >> 10;

    const float4* base = (const float4*)(psf + ((size_t)(n * C_CH + c) * HW) * HW);
    const int r[4] = {8 * i + 1, 8 * i + 2, 8 * i + 5, 8 * i + 6};

    float4 v[8];
#pragma unroll
    for (int a = 0; a < 4; a++) {
        v[2 * a]     = __ldg(base + r[a] * (HW / 4) + lane);
        v[2 * a + 1] = __ldg(base + r[a] * (HW / 4) + 32 + lane);
    }
    float plo[4], phi[4];
#pragma unroll
    for (int a = 0; a < 4; a++) {
        plo[a] = v[2 * a].y + v[2 * a].z;
        phi[a] = v[2 * a + 1].y + v[2 * a + 1].z;
    }
    // even lane 2j: (s00, s10); odd lane 2j+1: (s01, s11)
    float mlo = fmaxf(plo[0] + plo[1], plo[2] + plo[3]);
    float mhi = fmaxf(phi[0] + phi[1], phi[2] + phi[3]);
    mlo = fmaxf(mlo, __shfl_xor_sync(0xffffffffu, mlo, 1));
    mhi = fmaxf(mhi, __shfl_xor_sync(0xffffffffu, mhi, 1));

    if ((lane & 1) == 0) {
        float* ob = g_p + (size_t)g * 32;
        int j = lane >> 1;
        ob[j]      = 0.25f * mlo;   // cols 0..15
        ob[j + 16] = 0.25f * mhi;   // cols 16..31
    }
}

// ---------------------------------------------------------------------------
// Kernel B: thread = (n, c_out, pix); caches 32-ch p column in registers,
// computes all 9 taps -> g_y. float4 weight loads, 4 accumulators.
// ---------------------------------------------------------------------------
__global__ void __launch_bounds__(256) kB(const float* __restrict__ w1,
                                          const float* __restrict__ b1,
                                          const float* __restrict__ ws,
                                          const float* __restrict__ bs) {
    int t = blockIdx.x * blockDim.x + threadIdx.x;   // 131072
    int pix = t & 1023;
    int c = (t >> 10) & 31;
    int n = t >> 15;

    float pv[C_CH];
    const float* pb = g_p + (size_t)n * (C_CH * QS * QS) + pix;
#pragma unroll
    for (int ch = 0; ch < C_CH; ch++) pv[ch] = pb[ch * (QS * QS)];

    float* yb = g_y + (size_t)(n * OCH + c * KS2) * (QS * QS) + pix;
#pragma unroll
    for (int k = 0; k < KS2; k++) {
        const int o = c * KS2 + k;
        const float4* wr1 = (const float4*)(w1 + o * C_CH);
        const float4* wrs = (const float4*)(ws + o * C_CH);
        float a1lo = 0.f, a1hi = 0.f, a2lo = 0.f, a2hi = 0.f;
#pragma unroll
        for (int q = 0; q < C_CH / 4; q++) {
            float4 u = __ldg(wr1 + q);
            float4 s = __ldg(wrs + q);
            int ch = 4 * q;
            a1lo = fmaf(pv[ch + 0], u.x, a1lo);
            a1hi = fmaf(pv[ch + 1], u.y, a1hi);
            a1lo = fmaf(pv[ch + 2], u.z, a1lo);
            a1hi = fmaf(pv[ch + 3], u.w, a1hi);
            a2lo = fmaf(pv[ch + 0], s.x, a2lo);
            a2hi = fmaf(pv[ch + 1], s.y, a2hi);
            a2lo = fmaf(pv[ch + 2], s.z, a2lo);
            a2hi = fmaf(pv[ch + 3], s.w, a2hi);
        }
        float a1 = a1lo + a1hi + b1[o];
        float a2 = a2lo + a2hi + bs[o];
        float act = (a1 >= 0.f) ? a1 : 0.2f * a1;
        yb[k * (QS * QS)] = act + a2;
    }
}

// ---------------------------------------------------------------------------
// Kernel C (R1 verbatim — best measured): fused x8 bilinear upsample + FAC.
// ---------------------------------------------------------------------------
__global__ void __launch_bounds__(256) kC(const float* __restrict__ fm,
                                          float* __restrict__ out) {
    __shared__ float fmt[18][258];
    __shared__ float yt[KS2][4][32];

    const int tt = blockIdx.x;           // 0..15
    const int c  = blockIdx.y;
    const int n  = blockIdx.z;
    const int w  = threadIdx.x;
    const int h0 = tt * 16;
    const int crBase = 2 * tt - 1;

    const float* fbase = fm + ((size_t)(n * C_CH + c) * HW) * HW;
    for (int r = 0; r < 18; r++) {
        int gh = h0 - 1 + r;
        bool rowok = (gh >= 0) && (gh < HW);
        for (int col = w; col < 258; col += 256) {
            int gw = col - 1;
            float v = 0.f;
            if (rowok && gw >= 0 && gw < HW) v = fbase[gh * HW + gw];
            fmt[r][col] = v;
        }
    }

    const float* ybase = g_y + (size_t)(n * OCH + c * KS2) * (QS * QS);
    for (int idx = w; idx < 9 * 4 * 32; idx += 256) {
        int k = idx >> 7;
        int rem = idx & 127;
        int r = rem >> 5;
        int col = rem & 31;
        int cr = crBase + r;
        cr = min(max(cr, 0), QS - 1);
        yt[k][r][col] = ybase[k * (QS * QS) + cr * QS + col];
    }
    __syncthreads();

    int ix0 = (w - 4) >> 3;
    float wx = (float)w * 0.125f - 0.4375f - (float)ix0;
    int jx0 = max(ix0, 0);
    int jx1 = min(ix0 + 1, QS - 1);
    float hl[4][KS2];
#pragma unroll
    for (int r = 0; r < 4; r++) {
#pragma unroll
        for (int k = 0; k < KS2; k++) {
            float a = yt[k][r][jx0];
            float b = yt[k][r][jx1];
            hl[r][k] = a + wx * (b - a);
        }
    }

    float win[3][3];
#pragma unroll
    for (int d = 0; d < 3; d++) {
        win[0][d] = fmt[0][w + d];
        win[1][d] = fmt[1][w + d];
    }

    float* obase = out + (((size_t)(n * C_CH + c) * HW + h0) * HW) + w;

#pragma unroll
    for (int hh = 0; hh < 16; hh++) {
#pragma unroll
        for (int d = 0; d < 3; d++) win[2][d] = fmt[hh + 2][w + d];

        const int t0 = (hh < 4) ? 0 : ((hh < 12) ? 1 : 2);
        const float wy = (float)hh * 0.125f + 0.5625f - (float)t0;

        float acc = 0.f;
#pragma unroll
        for (int dy = 0; dy < 3; dy++) {
#pragma unroll
            for (int dx = 0; dx < 3; dx++) {
                int k = dy * 3 + dx;
                float ft = hl[t0][k] + wy * (hl[t0 + 1][k] - hl[t0][k]);
                acc = fmaf(ft, win[dy][dx], acc);
            }
        }
        obase[hh * HW] = acc;

#pragma unroll
        for (int d = 0; d < 3; d++) {
            win[0][d] = win[1][d];
            win[1][d] = win[2][d];
        }
    }
}

// ---------------------------------------------------------------------------
extern "C" void kernel_launch(void* const* d_in, const int* in_sizes, int n_in,
                              void* d_out, int out_size) {
    const float* psf = (const float*)d_in[0];
    const float* fm  = (const float*)d_in[1];
    const float* w1  = (const float*)d_in[2];
    const float* b1  = (const float*)d_in[3];
    const float* ws  = (const float*)d_in[4];
    const float* bs  = (const float*)d_in[5];
    float* out = (float*)d_out;

    kA<<<512, 256>>>(psf);
    kB<<<512, 256>>>(w1, b1, ws, bs);
    dim3 gc(16, C_CH, NB);
    kC<<<gc, 256>>>(fm, out);
}